// round 2
// baseline (speedup 1.0000x reference)
#include <cuda_runtime.h>

#define NN 4
#define CC 256
#define HS 64
#define WS 64
#define PIX 4096        // 64*64
#define COMPC 64
#define MC 100
#define KK2 25
#define HO 128
#define WO 128
#define OPIX 16384      // 128*128
#define BN_EPS 1e-5f

typedef unsigned long long ull;

// ---- packed f32x2 helpers (Blackwell FFMA2 path) ----
__device__ __forceinline__ ull dup2(float w) {
    ull r; asm("mov.b64 %0, {%1, %1};" : "=l"(r) : "f"(w)); return r;
}
__device__ __forceinline__ void fma2(ull& d, ull a, ull b) {
    asm("fma.rn.f32x2 %0, %1, %2, %0;" : "+l"(d) : "l"(a), "l"(b));
}
__device__ __forceinline__ ull add2(ull a, ull b) {
    ull r; asm("add.rn.f32x2 %0, %1, %2;" : "=l"(r) : "l"(a), "l"(b)); return r;
}
__device__ __forceinline__ float2 unpk(ull v) {
    float2 r; asm("mov.b64 {%0, %1}, %2;" : "=f"(r.x), "=f"(r.y) : "l"(v)); return r;
}

// ---------------- device scratch ----------------
__device__ float g_comp [NN * COMPC * PIX];
__device__ float g_mlog [NN * MC * PIX];
__device__ float g_maskp[NN * KK2 * OPIX];     // planar masks [n][k][i][j]
__device__ float g_y    [NN * CC * PIX];
__device__ float g_weff [CC * CC];
__device__ float g_beff [CC];
__device__ float g_sum  [CC];
__device__ float g_sumsq[CC];
__device__ float g_scale[CC];
__device__ float g_shift[CC];

// ---------------- K0: fold weights + zero BN accumulators ----------------
__global__ void k_fold(const float* __restrict__ wb,
                       const float* __restrict__ wc2,
                       const float* __restrict__ bc2) {
    int o = blockIdx.x;
    int c = threadIdx.x;
    const float* wbo = wb + o * 512;
    float acc = wbo[256 + c];
    for (int m = 0; m < 256; m++)
        acc += wbo[m] * wc2[m * 256 + c];
    g_weff[o * 256 + c] = acc;

    __shared__ float red[256];
    red[c] = wbo[c] * bc2[c];
    __syncthreads();
    for (int s = 128; s > 0; s >>= 1) {
        if (c < s) red[c] += red[c + s];
        __syncthreads();
    }
    if (c == 0) g_beff[o] = red[0];
    if (o == 0) { g_sum[c] = 0.f; g_sumsq[c] = 0.f; }
}

// ---------------- K1: merged compress(64) + ymix(256) GEMM, M=320 K=256 ----------------
// grid 320 = n(4) x pxtile(16 of 256) x mtile(5 of 64); 256 threads
// thread: 8 oc x 8 px register tile, FFMA2
__global__ __launch_bounds__(256) void k_gemm320(const float* __restrict__ hi,
                                                 const float* __restrict__ wcc,
                                                 const float* __restrict__ bcc) {
    int b  = blockIdx.x;
    int mt = b % 5;
    int pt = (b / 5) & 15;
    int n  = b / 80;
    int px0 = pt * 256;
    int tid = threadIdx.x;
    int tx = tid & 31, og = tid >> 5;
    int pxl = tx * 8, ocl = og * 8;

    __shared__ __align__(16) float ws[16][64];
    __shared__ __align__(16) float xs[16][256];

    ull acc[8][4];
    #pragma unroll
    for (int o = 0; o < 8; o++)
        #pragma unroll
        for (int p = 0; p < 4; p++) acc[o][p] = 0ull;

    int m_l = tid >> 2, kq = tid & 3;
    int m_g = mt * 64 + m_l;
    const float* wsrc = (m_g < 64) ? (wcc + m_g * 256) : (g_weff + (m_g - 64) * 256);
    const float* xsrc = hi + n * 256 * PIX + px0;

    for (int k0 = 0; k0 < 256; k0 += 16) {
        float4 wv = *(const float4*)(wsrc + k0 + kq * 4);
        float4 xv[4];
        #pragma unroll
        for (int l = 0; l < 4; l++) {
            int fi = tid + l * 256;
            int kr = fi >> 6, pq = fi & 63;
            xv[l] = *(const float4*)(xsrc + (k0 + kr) * PIX + pq * 4);
        }
        __syncthreads();
        ws[kq * 4 + 0][m_l] = wv.x;
        ws[kq * 4 + 1][m_l] = wv.y;
        ws[kq * 4 + 2][m_l] = wv.z;
        ws[kq * 4 + 3][m_l] = wv.w;
        #pragma unroll
        for (int l = 0; l < 4; l++) {
            int fi = tid + l * 256;
            int kr = fi >> 6, pq = fi & 63;
            *(float4*)&xs[kr][pq * 4] = xv[l];
        }
        __syncthreads();

        #pragma unroll
        for (int kr = 0; kr < 16; kr++) {
            const ull* xp = (const ull*)&xs[kr][pxl];
            ull x2[4] = { xp[0], xp[1], xp[2], xp[3] };
            float4 wa = *(const float4*)&ws[kr][ocl];
            float4 wb2 = *(const float4*)&ws[kr][ocl + 4];
            ull wd[8] = { dup2(wa.x), dup2(wa.y), dup2(wa.z), dup2(wa.w),
                          dup2(wb2.x), dup2(wb2.y), dup2(wb2.z), dup2(wb2.w) };
            #pragma unroll
            for (int o = 0; o < 8; o++) {
                fma2(acc[o][0], wd[o], x2[0]);
                fma2(acc[o][1], wd[o], x2[1]);
                fma2(acc[o][2], wd[o], x2[2]);
                fma2(acc[o][3], wd[o], x2[3]);
            }
        }
    }

    #pragma unroll
    for (int o = 0; o < 8; o++) {
        int m = mt * 64 + ocl + o;
        float2 u0 = unpk(acc[o][0]), u1 = unpk(acc[o][1]);
        float2 u2 = unpk(acc[o][2]), u3 = unpk(acc[o][3]);
        float bias = (m < 64) ? bcc[m] : 0.f;
        float4 v0 = make_float4(u0.x + bias, u0.y + bias, u1.x + bias, u1.y + bias);
        float4 v1 = make_float4(u2.x + bias, u2.y + bias, u3.x + bias, u3.y + bias);
        float* dst = (m < 64) ? (g_comp + (n * 64 + m) * PIX + px0 + pxl)
                              : (g_y + (n * 256 + (m - 64)) * PIX + px0 + pxl);
        *(float4*)(dst)     = v0;
        *(float4*)(dst + 4) = v1;
    }
}

// ---------------- K2: content encoder 3x3 (64 -> 100), ic-split register tile ----------------
// grid 256 = (n,h); 128 threads = ks(2, ic-halves) x og(4, 25 oc) x tx(16, 4 px)
__global__ __launch_bounds__(128) void k_encode(const float* __restrict__ wce,
                                                const float* __restrict__ bce) {
    int b = blockIdx.x; int n = b >> 6; int h = b & 63;
    int tid = threadIdx.x;
    int ks = tid >> 6;
    int og = (tid >> 4) & 3;
    int tx = tid & 15;
    int pxb = tx * 4;

    __shared__ __align__(16) float xs[2][4][3][66];    // [ks][cl][ky][x]
    __shared__ __align__(16) float ws[72 * 104];       // [(ks,cl,ky,kx)][oc padded 4x26]

    // zero pad columns once (col og*26+25 for every row)
    for (int i = tid; i < 288; i += 128)
        ws[(i >> 2) * 104 + (i & 3) * 26 + 25] = 0.f;

    ull acc[13][4];
    #pragma unroll
    for (int p = 0; p < 13; p++)
        #pragma unroll
        for (int q = 0; q < 4; q++) acc[p][q] = 0ull;

    for (int ch = 0; ch < 8; ch++) {
        __syncthreads();
        // load xs: 2*4*3*66 = 1584 entries
        for (int idx = tid; idx < 1584; idx += 128) {
            int ksl = idx / 792; int r = idx % 792;
            int cl = r / 198; int r2 = r % 198;
            int ky = r2 / 66; int x = r2 % 66;
            int ic = ksl * 32 + ch * 4 + cl;
            int gh = h - 1 + ky, gw = x - 1;
            float v = 0.f;
            if (gh >= 0 && gh < 64 && gw >= 0 && gw < 64)
                v = g_comp[((n * 64 + ic) * 64 + gh) * 64 + gw];
            xs[ksl][cl][ky][x] = v;
        }
        // load ws: 2*4*9*100 = 7200 entries
        for (int idx = tid; idx < 7200; idx += 128) {
            int oc = idx % 100; int t = idx / 100;
            int kx = t % 3; t /= 3;
            int ky = t % 3; t /= 3;
            int cl = t & 3; int ksl = t >> 2;
            int ic = ksl * 32 + ch * 4 + cl;
            ws[(((ksl * 4 + cl) * 3 + ky) * 3 + kx) * 104 + (oc / 25) * 26 + (oc % 25)]
                = wce[((oc * 64 + ic) * 3 + ky) * 3 + kx];
        }
        __syncthreads();

        for (int cl = 0; cl < 4; cl++) {
            #pragma unroll
            for (int ky = 0; ky < 3; ky++) {
                ull xd[6];
                #pragma unroll
                for (int i = 0; i < 6; i++) xd[i] = dup2(xs[ks][cl][ky][pxb + i]);
                #pragma unroll
                for (int kx = 0; kx < 3; kx++) {
                    const float* wr = ws + (((ks * 4 + cl) * 3 + ky) * 3 + kx) * 104 + og * 26;
                    #pragma unroll
                    for (int p = 0; p < 13; p++) {
                        ull w2 = *(const ull*)(wr + 2 * p);
                        fma2(acc[p][0], w2, xd[kx + 0]);
                        fma2(acc[p][1], w2, xd[kx + 1]);
                        fma2(acc[p][2], w2, xd[kx + 2]);
                        fma2(acc[p][3], w2, xd[kx + 3]);
                    }
                }
            }
        }
    }

    __syncthreads();
    // reduce the two ic-halves
    ull* red = (ull*)ws;
    if (ks == 1) {
        ull* dst = red + (og * 16 + tx) * 52;
        #pragma unroll
        for (int p = 0; p < 13; p++)
            #pragma unroll
            for (int q = 0; q < 4; q++) dst[p * 4 + q] = acc[p][q];
    }
    __syncthreads();
    if (ks == 0) {
        const ull* src = red + (og * 16 + tx) * 52;
        #pragma unroll
        for (int p = 0; p < 13; p++)
            #pragma unroll
            for (int q = 0; q < 4; q++) acc[p][q] = add2(acc[p][q], src[p * 4 + q]);

        #pragma unroll
        for (int p = 0; p < 13; p++) {
            int oc0 = og * 25 + 2 * p;
            float2 u0 = unpk(acc[p][0]), u1 = unpk(acc[p][1]);
            float2 u2 = unpk(acc[p][2]), u3 = unpk(acc[p][3]);
            float b0 = bce[oc0];
            float4 v = make_float4(u0.x + b0, u1.x + b0, u2.x + b0, u3.x + b0);
            *(float4*)(g_mlog + (n * 100 + oc0) * PIX + h * 64 + pxb) = v;
            if (2 * p + 1 < 25) {
                int oc1 = oc0 + 1;
                float b1 = bce[oc1];
                float4 w4 = make_float4(u0.y + b1, u1.y + b1, u2.y + b1, u3.y + b1);
                *(float4*)(g_mlog + (n * 100 + oc1) * PIX + h * 64 + pxb) = w4;
            }
        }
    }
}

// ---------------- K3: pixel-shuffle + softmax -> planar masks ----------------
__global__ void k_softmax() {
    int b = blockIdx.x; int n = b >> 6; int h = b & 63;
    int w = threadIdx.x;
    const float* base = g_mlog + (size_t)n * MC * PIX + h * 64 + w;
    for (int q = 0; q < 4; q++) {
        float v[25];
        float mx = -1e30f;
        #pragma unroll
        for (int k = 0; k < 25; k++) {
            v[k] = base[(k * 4 + q) * PIX];
            mx = fmaxf(mx, v[k]);
        }
        float s = 0.f;
        #pragma unroll
        for (int k = 0; k < 25; k++) { v[k] = __expf(v[k] - mx); s += v[k]; }
        float inv = 1.f / s;
        int i = 2 * h + (q >> 1), j = 2 * w + (q & 1);
        #pragma unroll
        for (int k = 0; k < 25; k++)
            g_maskp[(n * 25 + k) * OPIX + i * 128 + j] = v[k] * inv;
    }
}

// ---------------- K4: CARAFE (oc-transposed smem, FFMA2 over oc pairs) ----------------
// grid 2048 = (n, h, ocChunk of 32); 256 threads = j(128) x ocg(2, 16 oc each)
__global__ __launch_bounds__(256) void k_carafe(float* __restrict__ out) {
    int b = blockIdx.x;
    int n   = b >> 9;
    int h   = (b >> 3) & 63;
    int oc0 = (b & 7) * 32;
    int tid = threadIdx.x;
    int j   = tid & 127;
    int ocg = tid >> 7;
    int w   = j >> 1;

    __shared__ __align__(16) float ys[5][68][34];   // [dy][x][oc] oc-fastest
    for (int idx = tid; idx < 32 * 5 * 68; idx += 256) {
        int oc = idx / 340; int r = idx % 340; int dy = r / 68; int x = r % 68;
        int gh = h - 2 + dy, gw = x - 2;
        float v = 0.f;
        if (gh >= 0 && gh < 64 && gw >= 0 && gw < 64)
            v = g_y[((n * 256 + oc0 + oc) * 64 + gh) * 64 + gw];
        ys[dy][x][oc] = v;
    }
    __syncthreads();

    float m0[25], m1[25];
    const float* mp = g_maskp + (size_t)n * 25 * OPIX + (2 * h) * 128 + j;
    #pragma unroll
    for (int k = 0; k < 25; k++) { m0[k] = mp[k * OPIX]; m1[k] = mp[k * OPIX + 128]; }

    int ocb = ocg * 16;
    ull a0[8], a1[8];
    #pragma unroll
    for (int p = 0; p < 8; p++) { a0[p] = 0ull; a1[p] = 0ull; }

    #pragma unroll
    for (int dy = 0; dy < 5; dy++) {
        #pragma unroll
        for (int dx = 0; dx < 5; dx++) {
            const ull* yp = (const ull*)&ys[dy][w + dx][ocb];
            ull y[8] = { yp[0], yp[1], yp[2], yp[3], yp[4], yp[5], yp[6], yp[7] };
            ull d0 = dup2(m0[dy * 5 + dx]);
            ull d1 = dup2(m1[dy * 5 + dx]);
            #pragma unroll
            for (int p = 0; p < 8; p++) {
                fma2(a0[p], y[p], d0);
                fma2(a1[p], y[p], d1);
            }
        }
    }

    #pragma unroll
    for (int p = 0; p < 8; p++) {
        int oc = oc0 + ocb + 2 * p;
        float2 r0 = unpk(a0[p]);
        float2 r1 = unpk(a1[p]);
        float be0 = g_beff[oc], be1 = g_beff[oc + 1];
        int base0 = (n * 256 + oc) * OPIX + (2 * h) * 128 + j;
        out[base0]              = r0.x + be0;
        out[base0 + 128]        = r1.x + be0;
        out[base0 + OPIX]       = r0.y + be1;
        out[base0 + OPIX + 128] = r1.y + be1;
    }
}

// ---------------- K5a: BN reduction ----------------
__global__ void k_bnred(const float* __restrict__ x) {
    int b = blockIdx.x;
    int o = b & 255;
    const float* p = x + (size_t)b * OPIX;
    float s = 0.f, ss = 0.f;
    for (int idx = threadIdx.x; idx < OPIX; idx += 256) {
        float v = p[idx];
        s += v; ss += v * v;
    }
    #pragma unroll
    for (int off = 16; off > 0; off >>= 1) {
        s  += __shfl_down_sync(0xffffffffu, s, off);
        ss += __shfl_down_sync(0xffffffffu, ss, off);
    }
    __shared__ float rs[8], rss[8];
    if ((threadIdx.x & 31) == 0) { rs[threadIdx.x >> 5] = s; rss[threadIdx.x >> 5] = ss; }
    __syncthreads();
    if (threadIdx.x == 0) {
        float S = 0.f, SS = 0.f;
        #pragma unroll
        for (int i = 0; i < 8; i++) { S += rs[i]; SS += rss[i]; }
        atomicAdd(&g_sum[o], S);
        atomicAdd(&g_sumsq[o], SS);
    }
}

// ---------------- K5b: BN scale/shift ----------------
__global__ void k_bnparam(const float* __restrict__ gamma, const float* __restrict__ beta) {
    int o = threadIdx.x;
    float cnt = (float)(NN * HO * WO);
    float mean = g_sum[o] / cnt;
    float var  = g_sumsq[o] / cnt - mean * mean;
    float sc   = gamma[o] * rsqrtf(var + BN_EPS);
    g_scale[o] = sc;
    g_shift[o] = beta[o] - mean * sc;
}

// ---------------- K6: BN apply + ReLU ----------------
__global__ void k_bnapply(float* __restrict__ x) {
    int idx = blockIdx.x * 256 + threadIdx.x;
    int o = (idx >> 12) & 255;
    float4 v = reinterpret_cast<float4*>(x)[idx];
    float sc = g_scale[o], sh = g_shift[o];
    v.x = fmaxf(v.x * sc + sh, 0.f);
    v.y = fmaxf(v.y * sc + sh, 0.f);
    v.z = fmaxf(v.z * sc + sh, 0.f);
    v.w = fmaxf(v.w * sc + sh, 0.f);
    reinterpret_cast<float4*>(x)[idx] = v;
}

// ---------------- launcher ----------------
extern "C" void kernel_launch(void* const* d_in, const int* in_sizes, int n_in,
                              void* d_out, int out_size) {
    const float* high  = (const float*)d_in[1];
    const float* wcc   = (const float*)d_in[2];
    const float* bcc   = (const float*)d_in[3];
    const float* wce   = (const float*)d_in[4];
    const float* bce   = (const float*)d_in[5];
    const float* wc2   = (const float*)d_in[6];
    const float* bc2   = (const float*)d_in[7];
    const float* wb    = (const float*)d_in[8];
    const float* gamma = (const float*)d_in[9];
    const float* beta  = (const float*)d_in[10];
    float* out = (float*)d_out;

    k_fold    <<<256, 256>>>(wb, wc2, bc2);
    k_gemm320 <<<320, 256>>>(high, wcc, bcc);
    k_encode  <<<256, 128>>>(wce, bce);
    k_softmax <<<256, 64>>>();
    k_carafe  <<<2048, 256>>>(out);
    k_bnred   <<<1024, 256>>>(out);
    k_bnparam <<<1, 256>>>(gamma, beta);
    k_bnapply <<<16384, 256>>>(out);
}